// round 5
// baseline (speedup 1.0000x reference)
#include <cuda_runtime.h>
#include <math.h>

#define POINCARE_BOUND 0.99999f   // 1 - 1e-5
typedef unsigned long long u64;

// ---------------------------------------------------------------------------
// constant-memory weights: only the two input-branch matrices + biases.
// (Constant port has an 8-cycle LDC->LDC floor; keep its demand below the
//  FMA-pipe budget. W0/W1 go to shared memory instead.)
// ---------------------------------------------------------------------------
__constant__ __align__(16) float cWc1[32 * 64];
__constant__ __align__(16) float cWc2[32 * 64];
__constant__ __align__(16) float cbc [64];
__constant__ __align__(16) float cb0 [64];
__constant__ __align__(16) float cb1 [32];

// ---------------------------------------------------------------------------
// packed f32x2 primitives
// ---------------------------------------------------------------------------
__device__ __forceinline__ u64 pk2(float lo, float hi) {
    u64 r; asm("mov.b64 %0, {%1, %2};" : "=l"(r) : "f"(lo), "f"(hi)); return r;
}
__device__ __forceinline__ void upk2(u64 v, float& lo, float& hi) {
    asm("mov.b64 {%0, %1}, %2;" : "=f"(lo), "=f"(hi) : "l"(v));
}
__device__ __forceinline__ u64 fma2(u64 a, u64 b, u64 c) {
    u64 d; asm("fma.rn.f32x2 %0, %1, %2, %3;" : "=l"(d) : "l"(a), "l"(b), "l"(c)); return d;
}
__device__ __forceinline__ u64 mul2(u64 a, u64 b) {
    u64 d; asm("mul.rn.f32x2 %0, %1, %2;" : "=l"(d) : "l"(a), "l"(b)); return d;
}
__device__ __forceinline__ float hsum2(u64 v) {
    float lo, hi; upk2(v, lo, hi); return lo + hi;
}

// ---------------------------------------------------------------------------
// fast scalar math (MUFU approx; operand norms here are O(1), safe)
// ---------------------------------------------------------------------------
__device__ __forceinline__ float rcpf(float x)  { float r; asm("rcp.approx.f32 %0, %1;"  : "=f"(r) : "f"(x)); return r; }
__device__ __forceinline__ float sqrtfa(float x){ float r; asm("sqrt.approx.f32 %0, %1;" : "=f"(r) : "f"(x)); return r; }
__device__ __forceinline__ float lg2fa(float x) { float r; asm("lg2.approx.f32 %0, %1;"  : "=f"(r) : "f"(x)); return r; }
__device__ __forceinline__ float ex2fa(float x) { float r; asm("ex2.approx.f32 %0, %1;"  : "=f"(r) : "f"(x)); return r; }

__device__ __forceinline__ float log_scale(float ss) {   // atanh(min(n,B))/n
    float n  = fmaxf(sqrtfa(ss), 1e-15f);
    float m  = fminf(n, POINCARE_BOUND);
    float r  = (1.f + m) * rcpf(1.f - m);
    float at = 0.34657359f * lg2fa(r);                    // 0.5*ln(2)*log2(r)
    return at * rcpf(n);
}
__device__ __forceinline__ float exp_scale(float ss) {    // tanh(n)/n
    float n = fmaxf(sqrtfa(ss), 1e-15f);
    float e = ex2fa(n * -2.8853901f);                     // exp(-2n)
    float t = (1.f - e) * rcpf(1.f + e);
    return t * rcpf(n);
}

// ---------------------------------------------------------------------------
// packed vector ops (D2 = number of u64 = dims/2)
// ---------------------------------------------------------------------------
template<int D2>
__device__ __forceinline__ float ssum2(const u64* v) {
    u64 a = 0ull;
#pragma unroll
    for (int i = 0; i < D2; ++i) a = fma2(v[i], v[i], a);
    return hsum2(a);
}
template<int D2>
__device__ __forceinline__ void scale2(u64* v, float s) {
    const u64 s2 = pk2(s, s);
#pragma unroll
    for (int i = 0; i < D2; ++i) v[i] = mul2(v[i], s2);
}
template<int D2>
__device__ __forceinline__ void logmap0p(u64* v) { scale2<D2>(v, log_scale(ssum2<D2>(v))); }
template<int D2>
__device__ __forceinline__ void expmap0p(u64* v) { scale2<D2>(v, exp_scale(ssum2<D2>(v))); }

// x <- mobius_add(x, y); in-place on x. y may be constant memory or registers.
template<int D2>
__device__ __forceinline__ void mobius_addp(u64* x, const u64* y) {
    u64 ax = 0ull, ay = 0ull, axy = 0ull;
#pragma unroll
    for (int i = 0; i < D2; ++i) {
        u64 yi = y[i];
        ax  = fma2(x[i], x[i], ax);
        ay  = fma2(yi,  yi,  ay);
        axy = fma2(x[i], yi, axy);
    }
    float x2 = hsum2(ax), y2 = hsum2(ay), xy = hsum2(axy);
    float a   = 1.f + 2.f * xy + y2;
    float b   = 1.f - x2;
    float inv = rcpf(fmaxf(1.f + 2.f * xy + x2 * y2, 1e-15f));
    const u64 a2 = pk2(a * inv, a * inv);
    const u64 b2 = pk2(b * inv, b * inv);
#pragma unroll
    for (int i = 0; i < D2; ++i)
        x[i] = fma2(b2, y[i], mul2(a2, x[i]));
}

// o2[OUT/2] = v2[IN/2] @ W[IN][OUT]; W via 128-bit loads (LDC.128 or LDS.128,
// warp-uniform addresses). CH output columns per accumulation chunk.
template<int IN, int OUT, int CH>
__device__ __forceinline__ void matvec2(const u64* v2, const float* W, u64* o2) {
#pragma unroll
    for (int c0 = 0; c0 < OUT; c0 += CH) {
        u64 acc[CH / 2];
#pragma unroll
        for (int j = 0; j < CH / 2; ++j) acc[j] = 0ull;
#pragma unroll
        for (int k2 = 0; k2 < IN / 2; ++k2) {
            float lo, hi; upk2(v2[k2], lo, hi);
            const u64 va = pk2(lo, lo), vb = pk2(hi, hi);
            const ulonglong2* w0 = reinterpret_cast<const ulonglong2*>(W + (2 * k2)     * OUT + c0);
            const ulonglong2* w1 = reinterpret_cast<const ulonglong2*>(W + (2 * k2 + 1) * OUT + c0);
#pragma unroll
            for (int j = 0; j < CH / 4; ++j) {
                ulonglong2 wa = w0[j];
                acc[2 * j]     = fma2(va, wa.x, acc[2 * j]);
                acc[2 * j + 1] = fma2(va, wa.y, acc[2 * j + 1]);
                ulonglong2 wb = w1[j];
                acc[2 * j]     = fma2(vb, wb.x, acc[2 * j]);
                acc[2 * j + 1] = fma2(vb, wb.y, acc[2 * j + 1]);
            }
        }
#pragma unroll
        for (int j = 0; j < CH / 2; ++j) o2[c0 / 2 + j] = acc[j];
    }
}

// load one 32-wide row, pack, apply logmap0
__device__ __forceinline__ void load_log32p(const float* __restrict__ gx, int row, u64* v2) {
    const float4* xp = reinterpret_cast<const float4*>(gx + (size_t)row * 32);
    u64 a = 0ull;
#pragma unroll
    for (int i = 0; i < 8; ++i) {
        float4 v = xp[i];
        u64 p0 = pk2(v.x, v.y), p1 = pk2(v.z, v.w);
        v2[2 * i] = p0; v2[2 * i + 1] = p1;
        a = fma2(p0, p0, a);
        a = fma2(p1, p1, a);
    }
    scale2<16>(v2, log_scale(hsum2(a)));
}

// ---------------------------------------------------------------------------
// kernel: one thread per row; Wc1/Wc2 via constant port, W0/W1 via smem
// ---------------------------------------------------------------------------
__global__ void __launch_bounds__(128, 4)
poincare_mlp_kernel(const float* __restrict__ gx1,
                    const float* __restrict__ gx2,
                    const float* __restrict__ gW0,
                    const float* __restrict__ gW1,
                    float* __restrict__ gout,
                    int N)
{
    __shared__ __align__(16) float sW0[64 * 64];
    __shared__ __align__(16) float sW1[64 * 32];

    {   // cooperative fill: 6144 floats = 1536 float4, 128 threads -> 12 each
        const float4* g0 = reinterpret_cast<const float4*>(gW0);
        const float4* g1 = reinterpret_cast<const float4*>(gW1);
        float4* s0 = reinterpret_cast<float4*>(sW0);
        float4* s1 = reinterpret_cast<float4*>(sW1);
        const int t = threadIdx.x;
#pragma unroll
        for (int i = 0; i < 8; ++i) s0[t + 128 * i] = g0[t + 128 * i];
#pragma unroll
        for (int i = 0; i < 4; ++i) s1[t + 128 * i] = g1[t + 128 * i];
    }
    __syncthreads();

    const int row = blockIdx.x * 128 + threadIdx.x;
    if (row >= N) return;

    u64 u2[16];
    u64 h1[32], h2[32];

    // ---- branch 1: h1 = expmap0(logmap0(x1) @ Wc1)
    load_log32p(gx1, row, u2);
    matvec2<32, 64, 32>(u2, cWc1, h1);
    expmap0p<32>(h1);

    // ---- branch 2: h2 = expmap0(logmap0(x2) @ Wc2)
    load_log32p(gx2, row, u2);
    matvec2<32, 64, 32>(u2, cWc2, h2);
    expmap0p<32>(h2);

    // ---- h = mobius_add(mobius_add(h1, h2), bc)   (in place on h1)
    mobius_addp<32>(h1, h2);
    mobius_addp<32>(h1, reinterpret_cast<const u64*>(cbc));

    // ---- layer 0: mobius_add(expmap0(logmap0(h) @ W0), b0)
    logmap0p<32>(h1);
    matvec2<64, 64, 32>(h1, sW0, h2);
    expmap0p<32>(h2);
    mobius_addp<32>(h2, reinterpret_cast<const u64*>(cb0));

    // ---- layer 1: mobius_add(expmap0(logmap0(h) @ W1), b1)
    logmap0p<32>(h2);
    u64 o2[16];
    matvec2<64, 32, 32>(h2, sW1, o2);
    expmap0p<16>(o2);
    mobius_addp<16>(o2, reinterpret_cast<const u64*>(cb1));

    float4* op = reinterpret_cast<float4*>(gout + (size_t)row * 32);
#pragma unroll
    for (int i = 0; i < 8; ++i) {
        float x, y, z, w;
        upk2(o2[2 * i],     x, y);
        upk2(o2[2 * i + 1], z, w);
        op[i] = make_float4(x, y, z, w);
    }
}

// ---------------------------------------------------------------------------
// launch
// ---------------------------------------------------------------------------
extern "C" void kernel_launch(void* const* d_in, const int* in_sizes, int n_in,
                              void* d_out, int out_size)
{
    const float* x1 = (const float*)d_in[0];
    const float* x2 = (const float*)d_in[1];
    const float* W0 = (const float*)d_in[5];
    const float* W1 = (const float*)d_in[7];

    cudaMemcpyToSymbolAsync(cWc1, d_in[2], 32 * 64 * sizeof(float), 0, cudaMemcpyDeviceToDevice);
    cudaMemcpyToSymbolAsync(cWc2, d_in[3], 32 * 64 * sizeof(float), 0, cudaMemcpyDeviceToDevice);
    cudaMemcpyToSymbolAsync(cbc,  d_in[4], 64 * sizeof(float),      0, cudaMemcpyDeviceToDevice);
    cudaMemcpyToSymbolAsync(cb0,  d_in[6], 64 * sizeof(float),      0, cudaMemcpyDeviceToDevice);
    cudaMemcpyToSymbolAsync(cb1,  d_in[8], 32 * sizeof(float),      0, cudaMemcpyDeviceToDevice);

    float* out = (float*)d_out;
    const int N = in_sizes[0] / 32;
    const int blocks = (N + 127) / 128;
    poincare_mlp_kernel<<<blocks, 128>>>(x1, x2, W0, W1, out, N);
}